// round 4
// baseline (speedup 1.0000x reference)
#include <cuda_runtime.h>
#include <math.h>

#define BATCH   8
#define CHN     512
#define NPOS    9216         // 96*96
#define IMGW    96
#define HEADS   4
#define HD      128
#define QUARTER 2304         // NPOS/4
#define KV_SPLIT 18
#define KV_CHUNK 512         // NPOS / KV_SPLIT

// ---------------- scratch (device globals; no allocation allowed) -------------
__device__ float g_q[BATCH * CHN * NPOS];                       // 151 MB
__device__ float g_k[BATCH * CHN * NPOS];                       // 151 MB
__device__ float g_S[BATCH * HEADS * CHN];                      // quarter column sums of raw k
__device__ float g_kmean[BATCH * HEADS * HD];
__device__ float g_z[BATCH * HEADS * NPOS];
__device__ float g_kvp[BATCH * HEADS * KV_SPLIT * HD * HD];     // 37.7 MB
__device__ float g_kv[BATCH * HEADS * HD * HD];

__device__ __forceinline__ float elu1(float v) {
    return v > 0.f ? v + 1.f : expf(v);
}

// ============================================================================
// Kernel 1: per-batch GEMM  qk[b] (1024 x 9216) = W_qk (1024x512) @ x[b] (512x9216)
// fused bias + elu + 1.  Rows 0..511 -> g_q, rows 512..1023 -> g_k (channels-first).
// Block tile 128x128, K-tile 16, 256 threads, 8x8 microtile (4+4 split pattern).
// ============================================================================
__global__ __launch_bounds__(256) void qk_gemm_kernel(const float* __restrict__ x,
                                                      const float* __restrict__ Wqk,
                                                      const float* __restrict__ bqk) {
    __shared__ float As[16][132];   // [k][m]  (row stride mult. of 4 -> aligned LDS.128)
    __shared__ float Bs[16][128];   // [k][n]
    const int bN = blockIdx.x * 128;     // n offset
    const int bM = blockIdx.y * 128;     // out-channel offset
    const int bb = blockIdx.z;
    const float* X = x + (size_t)bb * CHN * NPOS;

    const int tid = threadIdx.x;
    const int tx = tid & 15, ty = tid >> 4;

    float acc[8][8];
#pragma unroll
    for (int i = 0; i < 8; i++)
#pragma unroll
        for (int j = 0; j < 8; j++) acc[i][j] = 0.f;

    for (int kt = 0; kt < CHN; kt += 16) {
        // A tile: 128 rows x 16 k  (W row-major over K) -> transposed into As[k][m]
#pragma unroll
        for (int r = 0; r < 2; r++) {
            int idx = tid + r * 256;           // 0..511
            int row = idx >> 2;
            int c4  = (idx & 3) * 4;
            float4 v = *(const float4*)&Wqk[(size_t)(bM + row) * CHN + kt + c4];
            As[c4 + 0][row] = v.x;
            As[c4 + 1][row] = v.y;
            As[c4 + 2][row] = v.z;
            As[c4 + 3][row] = v.w;
        }
        // B tile: 16 k-rows x 128 n, contiguous float4
#pragma unroll
        for (int r = 0; r < 2; r++) {
            int idx = tid + r * 256;
            int kk = idx >> 5;
            int c4 = (idx & 31) * 4;
            *(float4*)&Bs[kk][c4] = *(const float4*)&X[(size_t)(kt + kk) * NPOS + bN + c4];
        }
        __syncthreads();

#pragma unroll
        for (int kk = 0; kk < 16; kk++) {
            float a[8], bv[8];
            *(float4*)&a[0]  = *(const float4*)&As[kk][ty * 4];
            *(float4*)&a[4]  = *(const float4*)&As[kk][64 + ty * 4];
            *(float4*)&bv[0] = *(const float4*)&Bs[kk][tx * 4];
            *(float4*)&bv[4] = *(const float4*)&Bs[kk][64 + tx * 4];
#pragma unroll
            for (int i = 0; i < 8; i++)
#pragma unroll
                for (int j = 0; j < 8; j++) acc[i][j] += a[i] * bv[j];
        }
        __syncthreads();
    }

    // epilogue: bias + elu + 1, route to q or k buffer (channels-first)
#pragma unroll
    for (int ih = 0; ih < 2; ih++) {
#pragma unroll
        for (int i2 = 0; i2 < 4; i2++) {
            int i = ih * 4 + i2;
            int row = bM + ih * 64 + ty * 4 + i2;
            float bvv = bqk[row];
            float* dst = (row < CHN)
                ? &g_q[((size_t)bb * CHN + row) * NPOS]
                : &g_k[((size_t)bb * CHN + (row - CHN)) * NPOS];
#pragma unroll
            for (int jh = 0; jh < 2; jh++) {
                int col = bN + jh * 64 + tx * 4;
                float4 o;
                o.x = elu1(acc[i][jh * 4 + 0] + bvv);
                o.y = elu1(acc[i][jh * 4 + 1] + bvv);
                o.z = elu1(acc[i][jh * 4 + 2] + bvv);
                o.w = elu1(acc[i][jh * 4 + 3] + bvv);
                *(float4*)&dst[col] = o;
            }
        }
    }
}

// ============================================================================
// Kernel 2a: per-(b, channel) quarter-n sums of raw k:
//   g_S[b][q][c] = sum_{r in quarter q} k[b][c][r]
// ============================================================================
__global__ __launch_bounds__(256) void colsum_kernel() {
    const int c = blockIdx.x, bb = blockIdx.y;
    const float* src = &g_k[((size_t)bb * CHN + c) * NPOS];
    const int tid = threadIdx.x;
    const int q = tid >> 6, l = tid & 63;
    float s = 0.f;
#pragma unroll
    for (int i = 0; i < 36; i++) s += src[q * QUARTER + l + 64 * i];
    __shared__ float red[256];
    red[tid] = s;
    __syncthreads();
#pragma unroll
    for (int off = 32; off >= 1; off >>= 1) {
        if (l < off) red[tid] += red[tid + off];
        __syncthreads();
    }
    if (l == 0) g_S[((size_t)bb * HEADS + q) * CHN + c] = red[tid];
}

// Kernel 2b: k_mean[b][hh][d] = (S[hh][d] + S[hh][128+d] + S[hh][256+d] + S[hh][384+d]) / n
__global__ void kmean_kernel() {
    int idx = blockIdx.x * 256 + threadIdx.x;   // 4096 total
    if (idx >= BATCH * HEADS * HD) return;
    int d  = idx & 127;
    int hh = (idx >> 7) & 3;
    int bb = idx >> 9;
    const float* S = &g_S[((size_t)bb * HEADS + hh) * CHN];
    g_kmean[idx] = (S[d] + S[128 + d] + S[256 + d] + S[384 + d]) * (1.f / NPOS);
}

// ============================================================================
// Kernel 3: z[b][hh][m] = 1 / (sum_d q_raw[b][128*(m%4)+d][hh*2304+m/4] * kmean[d] + eps)
// One thread handles one r' = m/4 and all 4 residues j = m%4 (coalesced over r').
// ============================================================================
__global__ __launch_bounds__(256) void z_kernel() {
    const int chunk = blockIdx.x;                // 0..8  (2304/256)
    const int hh = blockIdx.y, bb = blockIdx.z;
    const int tid = threadIdx.x;
    __shared__ float km[HD];
    if (tid < HD) km[tid] = g_kmean[((size_t)bb * HEADS + hh) * HD + tid];
    __syncthreads();
    const int rp = chunk * 256 + tid;            // r' in [0,2304)
    const float* qbase = g_q + (size_t)bb * CHN * NPOS + (size_t)hh * QUARTER + rp;
    float a0 = 0.f, a1 = 0.f, a2 = 0.f, a3 = 0.f;
#pragma unroll 4
    for (int d = 0; d < HD; d++) {
        float kmv = km[d];
        a0 += qbase[(size_t)(d)       * NPOS] * kmv;
        a1 += qbase[(size_t)(128 + d) * NPOS] * kmv;
        a2 += qbase[(size_t)(256 + d) * NPOS] * kmv;
        a3 += qbase[(size_t)(384 + d) * NPOS] * kmv;
    }
    float* zb = &g_z[((size_t)bb * HEADS + hh) * NPOS + 4 * rp];
    zb[0] = 1.f / (a0 + 1e-6f);
    zb[1] = 1.f / (a1 + 1e-6f);
    zb[2] = 1.f / (a2 + 1e-6f);
    zb[3] = 1.f / (a3 + 1e-6f);
}

// ============================================================================
// Kernel 4: in-place RoPE on g_q and g_k (channels-first).
// Pair p rotates channels (2p, 2p+1).
// NOTE: the reference's (h, c/2) cos/sin broadcasts against the *w* axis of
// (b, h, w, c/2) -> angle is indexed by the COLUMN (pos % 96), not the row.
// ============================================================================
__global__ __launch_bounds__(256) void rope_kernel() {
    const int pos = blockIdx.x * 256 + threadIdx.x;   // < 9216
    const int p = blockIdx.y;                          // 0..255
    const int zb = blockIdx.z;                         // 0..15
    const int bb = zb >> 1;
    float* buf = (zb & 1) ? g_k : g_q;
    const int col = pos % IMGW;                        // w index (broadcast axis)
    // theta = 10000^(-p/256) = exp(-p * ln(1e4)/256)
    float theta = expf((float)p * (-9.210340371976184f / 256.f));
    float ang = (float)col * theta;
    float s, c;
    sincosf(ang, &s, &c);
    size_t base = ((size_t)bb * CHN + 2 * p) * NPOS + pos;
    float re = buf[base];
    float im = buf[base + NPOS];
    buf[base]        = c * re - s * im;
    buf[base + NPOS] = s * re + c * im;
}

// ============================================================================
// Kernel 5: kv partials.  Per (b, hh, chunk): 128x128 partial over 512 m.
//   kv[d][e] += k_rope[b][128hh+d][m] * x[b][128*(m%4)+e][hh*2304 + m/4]
// m-tile = 32 (8 r' x 4 j).  A loaded as float4 along m (covers all j at once).
// ============================================================================
__global__ __launch_bounds__(256) void kv_kernel(const float* __restrict__ x) {
    const int chunk = blockIdx.x;                 // 0..17
    const int hh = blockIdx.y, bb = blockIdx.z;
    __shared__ float As[32][132];   // [m][d]
    __shared__ float Bs[32][132];   // [m][e]
    const int tid = threadIdx.x;
    const int tx = tid & 15, ty = tid >> 4;

    float acc[8][8];
#pragma unroll
    for (int i = 0; i < 8; i++)
#pragma unroll
        for (int j = 0; j < 8; j++) acc[i][j] = 0.f;

    const float* kr = &g_k[((size_t)bb * CHN + 128 * hh) * NPOS];

    for (int t = 0; t < KV_CHUNK / 32; t++) {      // 16 m-tiles
        const int m0 = chunk * KV_CHUNK + t * 32;
        const int posb = hh * QUARTER + (m0 >> 2); // r' base

        // A: k_rope rows d, float4 along m.  g = m-group (8), d = tid>>3 + 32r
        {
            int g = tid & 7;
            int dbase = tid >> 3;
#pragma unroll
            for (int r = 0; r < 4; r++) {
                int d = dbase + 32 * r;
                float4 v = *(const float4*)&kr[(size_t)d * NPOS + m0 + g * 4];
                As[g * 4 + 0][d] = v.x;
                As[g * 4 + 1][d] = v.y;
                As[g * 4 + 2][d] = v.z;
                As[g * 4 + 3][d] = v.w;
            }
        }
        // B: x channels 128j+e, float4 along r'.  m = 4*r'_local + j
        {
            int rg = tid & 1;
            int j  = (tid >> 1) & 3;
            int ebase = tid >> 3;
#pragma unroll
            for (int r = 0; r < 4; r++) {
                int e = ebase + 32 * r;
                const float* px = x + ((size_t)bb * CHN + 128 * j + e) * NPOS + posb + rg * 4;
                float4 v = *(const float4*)px;
                Bs[(rg * 4 + 0) * 4 + j][e] = v.x;
                Bs[(rg * 4 + 1) * 4 + j][e] = v.y;
                Bs[(rg * 4 + 2) * 4 + j][e] = v.z;
                Bs[(rg * 4 + 3) * 4 + j][e] = v.w;
            }
        }
        __syncthreads();

#pragma unroll
        for (int m = 0; m < 32; m++) {
            float a[8], bv[8];
            *(float4*)&a[0]  = *(const float4*)&As[m][ty * 4];
            *(float4*)&a[4]  = *(const float4*)&As[m][64 + ty * 4];
            *(float4*)&bv[0] = *(const float4*)&Bs[m][tx * 4];
            *(float4*)&bv[4] = *(const float4*)&Bs[m][64 + tx * 4];
#pragma unroll
            for (int i = 0; i < 8; i++)
#pragma unroll
                for (int j = 0; j < 8; j++) acc[i][j] += a[i] * bv[j];
        }
        __syncthreads();
    }

    float* dst = &g_kvp[(((size_t)(bb * HEADS + hh)) * KV_SPLIT + chunk) * HD * HD];
#pragma unroll
    for (int ih = 0; ih < 2; ih++) {
#pragma unroll
        for (int i2 = 0; i2 < 4; i2++) {
            int i = ih * 4 + i2;
            int d = ih * 64 + ty * 4 + i2;
#pragma unroll
            for (int jh = 0; jh < 2; jh++) {
                float4 o;
                o.x = acc[i][jh * 4 + 0];
                o.y = acc[i][jh * 4 + 1];
                o.z = acc[i][jh * 4 + 2];
                o.w = acc[i][jh * 4 + 3];
                *(float4*)&dst[d * HD + jh * 64 + tx * 4] = o;
            }
        }
    }
}

// Kernel 5b: deterministic split reduce, fold scale^2 = 1/n
__global__ void kvreduce_kernel() {
    int idx = blockIdx.x * 256 + threadIdx.x;   // 524288 total
    int bh  = idx >> 14;                         // /16384
    int off = idx & 16383;
    const float* p = &g_kvp[((size_t)bh * KV_SPLIT) * HD * HD + off];
    float s = 0.f;
#pragma unroll
    for (int c = 0; c < KV_SPLIT; c++) s += p[(size_t)c * HD * HD];
    g_kv[idx] = s * (1.f / NPOS);
}

// ============================================================================
// Kernel 6: out[b][128hh+e][m] = z[b][hh][m] * sum_d q_rope[b][128hh+d][m] * kv[d][e]
// Per (b,hh): (9216 x 128) = q_rope^T @ kv, K = 128 in chunks of 16.
// ============================================================================
__global__ __launch_bounds__(256) void out_kernel(float* __restrict__ out) {
    const int m0 = blockIdx.x * 128;             // 72 m-tiles
    const int hh = blockIdx.y, bb = blockIdx.z;
    __shared__ float Qs[16][132];   // [dk][m]
    __shared__ float Es[16][132];   // [dk][e]
    const int tid = threadIdx.x;
    const int tx = tid & 15, ty = tid >> 4;

    float acc[8][8];
#pragma unroll
    for (int i = 0; i < 8; i++)
#pragma unroll
        for (int j = 0; j < 8; j++) acc[i][j] = 0.f;

    const float* qr = &g_q[((size_t)bb * CHN + 128 * hh) * NPOS];
    const float* kv = &g_kv[((size_t)(bb * HEADS) + hh) * HD * HD];

    for (int d0 = 0; d0 < HD; d0 += 16) {
#pragma unroll
        for (int r = 0; r < 2; r++) {
            int idx = tid + r * 256;
            int dk = idx >> 5;
            int mg = (idx & 31) * 4;
            *(float4*)&Qs[dk][mg] = *(const float4*)&qr[(size_t)(d0 + dk) * NPOS + m0 + mg];
            *(float4*)&Es[dk][mg] = *(const float4*)&kv[(d0 + dk) * HD + mg];
        }
        __syncthreads();
#pragma unroll
        for (int dk = 0; dk < 16; dk++) {
            float ev[8], mv[8];
            *(float4*)&ev[0] = *(const float4*)&Es[dk][ty * 4];
            *(float4*)&ev[4] = *(const float4*)&Es[dk][64 + ty * 4];
            *(float4*)&mv[0] = *(const float4*)&Qs[dk][tx * 4];
            *(float4*)&mv[4] = *(const float4*)&Qs[dk][64 + tx * 4];
#pragma unroll
            for (int i = 0; i < 8; i++)
#pragma unroll
                for (int j = 0; j < 8; j++) acc[i][j] += ev[i] * mv[j];
        }
        __syncthreads();
    }

    const float* zb = &g_z[((size_t)bb * HEADS + hh) * NPOS + m0];
#pragma unroll
    for (int ih = 0; ih < 2; ih++) {
#pragma unroll
        for (int i2 = 0; i2 < 4; i2++) {
            int i = ih * 4 + i2;
            int e = ih * 64 + ty * 4 + i2;
            float* dst = out + ((size_t)bb * CHN + 128 * hh + e) * NPOS + m0;
#pragma unroll
            for (int jh = 0; jh < 2; jh++) {
                int mc = jh * 64 + tx * 4;
                float4 o;
                o.x = acc[i][jh * 4 + 0] * zb[mc + 0];
                o.y = acc[i][jh * 4 + 1] * zb[mc + 1];
                o.z = acc[i][jh * 4 + 2] * zb[mc + 2];
                o.w = acc[i][jh * 4 + 3] * zb[mc + 3];
                *(float4*)&dst[mc] = o;
            }
        }
    }
}

// ============================================================================
// Kernel 7: lepe — depthwise 3x3 'SAME' conv on x, out += conv + bias.
// One block per (channel, batch); whole 96x96 plane in smem.
// ============================================================================
__global__ __launch_bounds__(256) void lepe_kernel(const float* __restrict__ x,
                                                   const float* __restrict__ w,
                                                   const float* __restrict__ bias,
                                                   float* __restrict__ out) {
    const int c = blockIdx.x, bb = blockIdx.y;
    __shared__ float plane[NPOS];
    const float* src = x + ((size_t)bb * CHN + c) * NPOS;
    const int tid = threadIdx.x;
    for (int i = tid; i < NPOS; i += 256) plane[i] = src[i];
    float wv[9];
#pragma unroll
    for (int kk = 0; kk < 9; kk++) wv[kk] = w[c * 9 + kk];
    const float bv = bias[c];
    __syncthreads();

    float* dst = out + ((size_t)bb * CHN + c) * NPOS;
    for (int i = tid; i < NPOS; i += 256) {
        int y = i / IMGW;
        int xx = i - y * IMGW;
        float s = bv;
#pragma unroll
        for (int ky = 0; ky < 3; ky++) {
            int yy = y + ky - 1;
            if (yy < 0 || yy >= IMGW) continue;
#pragma unroll
            for (int kx = 0; kx < 3; kx++) {
                int xs = xx + kx - 1;
                if (xs < 0 || xs >= IMGW) continue;
                s += wv[ky * 3 + kx] * plane[yy * IMGW + xs];
            }
        }
        dst[i] += s;
    }
}

// ============================================================================
extern "C" void kernel_launch(void* const* d_in, const int* in_sizes, int n_in,
                              void* d_out, int out_size) {
    (void)in_sizes; (void)n_in; (void)out_size;
    const float* x    = (const float*)d_in[0];
    const float* Wqk  = (const float*)d_in[1];
    const float* bqk  = (const float*)d_in[2];
    const float* lw   = (const float*)d_in[3];
    const float* lb   = (const float*)d_in[4];
    float* out = (float*)d_out;

    // 1) q,k = elu(W_qk @ x + b) + 1, channels-first
    qk_gemm_kernel<<<dim3(72, 8, BATCH), 256>>>(x, Wqk, bqk);
    // 2) k_mean (raw k)
    colsum_kernel<<<dim3(CHN, BATCH), 256>>>();
    kmean_kernel<<<16, 256>>>();
    // 3) z (raw q)
    z_kernel<<<dim3(9, HEADS, BATCH), 256>>>();
    // 4) RoPE in place (after raw consumers)
    rope_kernel<<<dim3(NPOS / 256, CHN / 2, BATCH * 2), 256>>>();
    // 5) kv = (k_rope/sqrt(n)) @ (v/sqrt(n))   (split-K + deterministic reduce)
    kv_kernel<<<dim3(KV_SPLIT, HEADS, BATCH), 256>>>(x);
    kvreduce_kernel<<<2048, 256>>>();
    // 6) out = z * (q_rope @ kv)
    out_kernel<<<dim3(72, HEADS, BATCH), 256>>>(out);
    // 7) out += depthwise3x3(x) + bias
    lepe_kernel<<<dim3(CHN, BATCH), 256>>>(x, lw, lb, out);
}

// round 8
// speedup vs baseline: 1.0682x; 1.0682x over previous
#include <cuda_runtime.h>
#include <math.h>
#include <stdint.h>

#define BATCH   8
#define CHN     512
#define NPOS    9216         // 96*96
#define IMGW    96
#define HEADS   4
#define HD      128
#define QUARTER 2304         // NPOS/4
#define KV_SPLIT 18
#define KV_CHUNK 512         // NPOS / KV_SPLIT

// ---------------- scratch (device globals; no allocation allowed) -------------
__device__ float g_q[BATCH * CHN * NPOS];                       // 151 MB
__device__ float g_k[BATCH * CHN * NPOS];                       // 151 MB
__device__ float g_S[BATCH * HEADS * CHN];
__device__ float g_kmean[BATCH * HEADS * HD];
__device__ float g_z[BATCH * HEADS * NPOS];
__device__ float g_kvp[BATCH * HEADS * KV_SPLIT * HD * HD];     // 37.7 MB
__device__ float g_kv[BATCH * HEADS * HD * HD];

__device__ __forceinline__ float elu1(float v) {
    return v > 0.f ? v + 1.f : expf(v);
}

// ---------------- packed f32x2 helpers (Blackwell sm_103a) --------------------
__device__ __forceinline__ unsigned long long pack2(float lo, float hi) {
    unsigned long long r;
    asm("mov.b64 %0, {%1, %2};" : "=l"(r) : "f"(lo), "f"(hi));
    return r;
}
__device__ __forceinline__ void unpack2(unsigned long long v, float& lo, float& hi) {
    asm("mov.b64 {%0, %1}, %2;" : "=f"(lo), "=f"(hi) : "l"(v));
}
// d = a * b + d  (two independent IEEE fp32 FMAs per issue slot)
__device__ __forceinline__ void ffma2(unsigned long long& d,
                                      unsigned long long a, unsigned long long b) {
    asm("fma.rn.f32x2 %0, %1, %2, %0;" : "+l"(d) : "l"(a), "l"(b));
}

// ============================================================================
// Kernel 1: per-batch GEMM  qk[b] (1024 x 9216) = W_qk (1024x512) @ x[b] (512x9216)
// fused bias + elu + 1.  Rows 0..511 -> g_q, rows 512..1023 -> g_k (channels-first).
// Block tile 128x128, K-tile 16, 256 threads, 8x8 microtile via fma.rn.f32x2.
// ============================================================================
__global__ __launch_bounds__(256) void qk_gemm_kernel(const float* __restrict__ x,
                                                      const float* __restrict__ Wqk,
                                                      const float* __restrict__ bqk) {
    __shared__ float As[16][132];   // [k][m]
    __shared__ float Bs[16][128];   // [k][n]
    const int bN = blockIdx.x * 128;     // n offset
    const int bM = blockIdx.y * 128;     // out-channel offset
    const int bb = blockIdx.z;
    const float* X = x + (size_t)bb * CHN * NPOS;

    const int tid = threadIdx.x;
    const int tx = tid & 15, ty = tid >> 4;

    unsigned long long acc2[8][4];     // [i][j-pair], packed fp32x2
#pragma unroll
    for (int i = 0; i < 8; i++)
#pragma unroll
        for (int j = 0; j < 4; j++) acc2[i][j] = 0ull;

    for (int kt = 0; kt < CHN; kt += 16) {
        // A tile: 128 rows x 16 k (W row-major over K) -> transposed into As[k][m]
#pragma unroll
        for (int r = 0; r < 2; r++) {
            int idx = tid + r * 256;           // 0..511
            int row = idx >> 2;
            int c4  = (idx & 3) * 4;
            float4 v = *(const float4*)&Wqk[(size_t)(bM + row) * CHN + kt + c4];
            As[c4 + 0][row] = v.x;
            As[c4 + 1][row] = v.y;
            As[c4 + 2][row] = v.z;
            As[c4 + 3][row] = v.w;
        }
        // B tile: 16 k-rows x 128 n, contiguous float4
#pragma unroll
        for (int r = 0; r < 2; r++) {
            int idx = tid + r * 256;
            int kk = idx >> 5;
            int c4 = (idx & 31) * 4;
            *(float4*)&Bs[kk][c4] = *(const float4*)&X[(size_t)(kt + kk) * NPOS + bN + c4];
        }
        __syncthreads();

#pragma unroll
        for (int kk = 0; kk < 16; kk++) {
            float a[8];
            *(float4*)&a[0]  = *(const float4*)&As[kk][ty * 4];
            *(float4*)&a[4]  = *(const float4*)&As[kk][64 + ty * 4];
            float4 b0 = *(const float4*)&Bs[kk][tx * 4];
            float4 b1 = *(const float4*)&Bs[kk][64 + tx * 4];
            unsigned long long bb4[4];
            bb4[0] = pack2(b0.x, b0.y);
            bb4[1] = pack2(b0.z, b0.w);
            bb4[2] = pack2(b1.x, b1.y);
            bb4[3] = pack2(b1.z, b1.w);
#pragma unroll
            for (int i = 0; i < 8; i++) {
                unsigned long long aa = pack2(a[i], a[i]);
                ffma2(acc2[i][0], aa, bb4[0]);
                ffma2(acc2[i][1], aa, bb4[1]);
                ffma2(acc2[i][2], aa, bb4[2]);
                ffma2(acc2[i][3], aa, bb4[3]);
            }
        }
        __syncthreads();
    }

    // epilogue: bias + elu + 1, route to q or k buffer (channels-first)
#pragma unroll
    for (int ih = 0; ih < 2; ih++) {
#pragma unroll
        for (int i2 = 0; i2 < 4; i2++) {
            int i = ih * 4 + i2;
            int row = bM + ih * 64 + ty * 4 + i2;
            float bvv = bqk[row];
            float* dst = (row < CHN)
                ? &g_q[((size_t)bb * CHN + row) * NPOS]
                : &g_k[((size_t)bb * CHN + (row - CHN)) * NPOS];
#pragma unroll
            for (int jh = 0; jh < 2; jh++) {
                int col = bN + jh * 64 + tx * 4;
                float lo0, hi0, lo1, hi1;
                unpack2(acc2[i][jh * 2 + 0], lo0, hi0);
                unpack2(acc2[i][jh * 2 + 1], lo1, hi1);
                float4 o;
                o.x = elu1(lo0 + bvv);
                o.y = elu1(hi0 + bvv);
                o.z = elu1(lo1 + bvv);
                o.w = elu1(hi1 + bvv);
                *(float4*)&dst[col] = o;
            }
        }
    }
}

// ============================================================================
// Kernel 2a: per-(b, channel) quarter-n sums of raw k
// ============================================================================
__global__ __launch_bounds__(256) void colsum_kernel() {
    const int c = blockIdx.x, bb = blockIdx.y;
    const float* src = &g_k[((size_t)bb * CHN + c) * NPOS];
    const int tid = threadIdx.x;
    const int q = tid >> 6, l = tid & 63;
    float s = 0.f;
#pragma unroll
    for (int i = 0; i < 36; i++) s += src[q * QUARTER + l + 64 * i];
    __shared__ float red[256];
    red[tid] = s;
    __syncthreads();
#pragma unroll
    for (int off = 32; off >= 1; off >>= 1) {
        if (l < off) red[tid] += red[tid + off];
        __syncthreads();
    }
    if (l == 0) g_S[((size_t)bb * HEADS + q) * CHN + c] = red[tid];
}

__global__ void kmean_kernel() {
    int idx = blockIdx.x * 256 + threadIdx.x;
    if (idx >= BATCH * HEADS * HD) return;
    int d  = idx & 127;
    int hh = (idx >> 7) & 3;
    int bb = idx >> 9;
    const float* S = &g_S[((size_t)bb * HEADS + hh) * CHN];
    g_kmean[idx] = (S[d] + S[128 + d] + S[256 + d] + S[384 + d]) * (1.f / NPOS);
}

// ============================================================================
// Kernel 3: z = 1 / (q_raw . k_mean + eps)
// ============================================================================
__global__ __launch_bounds__(256) void z_kernel() {
    const int chunk = blockIdx.x;
    const int hh = blockIdx.y, bb = blockIdx.z;
    const int tid = threadIdx.x;
    __shared__ float km[HD];
    if (tid < HD) km[tid] = g_kmean[((size_t)bb * HEADS + hh) * HD + tid];
    __syncthreads();
    const int rp = chunk * 256 + tid;
    const float* qbase = g_q + (size_t)bb * CHN * NPOS + (size_t)hh * QUARTER + rp;
    float a0 = 0.f, a1 = 0.f, a2 = 0.f, a3 = 0.f;
#pragma unroll 4
    for (int d = 0; d < HD; d++) {
        float kmv = km[d];
        a0 += qbase[(size_t)(d)       * NPOS] * kmv;
        a1 += qbase[(size_t)(128 + d) * NPOS] * kmv;
        a2 += qbase[(size_t)(256 + d) * NPOS] * kmv;
        a3 += qbase[(size_t)(384 + d) * NPOS] * kmv;
    }
    float* zb = &g_z[((size_t)bb * HEADS + hh) * NPOS + 4 * rp];
    zb[0] = 1.f / (a0 + 1e-6f);
    zb[1] = 1.f / (a1 + 1e-6f);
    zb[2] = 1.f / (a2 + 1e-6f);
    zb[3] = 1.f / (a3 + 1e-6f);
}

// ============================================================================
// Kernel 4: in-place RoPE; angle indexed by COLUMN (pos % 96) per reference broadcast
// ============================================================================
__global__ __launch_bounds__(256) void rope_kernel() {
    const int pos = blockIdx.x * 256 + threadIdx.x;
    const int p = blockIdx.y;
    const int zb = blockIdx.z;
    const int bb = zb >> 1;
    float* buf = (zb & 1) ? g_k : g_q;
    const int col = pos % IMGW;
    float theta = expf((float)p * (-9.210340371976184f / 256.f));
    float ang = (float)col * theta;
    float s, c;
    sincosf(ang, &s, &c);
    size_t base = ((size_t)bb * CHN + 2 * p) * NPOS + pos;
    float re = buf[base];
    float im = buf[base + NPOS];
    buf[base]        = c * re - s * im;
    buf[base + NPOS] = s * re + c * im;
}

// ============================================================================
// Kernel 5: kv partials (split-K, fma.rn.f32x2 microkernel)
// ============================================================================
__global__ __launch_bounds__(256) void kv_kernel(const float* __restrict__ x) {
    const int chunk = blockIdx.x;
    const int hh = blockIdx.y, bb = blockIdx.z;
    __shared__ float As[32][132];
    __shared__ float Bs[32][132];
    const int tid = threadIdx.x;
    const int tx = tid & 15, ty = tid >> 4;

    unsigned long long acc2[8][4];
#pragma unroll
    for (int i = 0; i < 8; i++)
#pragma unroll
        for (int j = 0; j < 4; j++) acc2[i][j] = 0ull;

    const float* kr = &g_k[((size_t)bb * CHN + 128 * hh) * NPOS];

    for (int t = 0; t < KV_CHUNK / 32; t++) {
        const int m0 = chunk * KV_CHUNK + t * 32;
        const int posb = hh * QUARTER + (m0 >> 2);
        {
            int g = tid & 7;
            int dbase = tid >> 3;
#pragma unroll
            for (int r = 0; r < 4; r++) {
                int d = dbase + 32 * r;
                float4 v = *(const float4*)&kr[(size_t)d * NPOS + m0 + g * 4];
                As[g * 4 + 0][d] = v.x;
                As[g * 4 + 1][d] = v.y;
                As[g * 4 + 2][d] = v.z;
                As[g * 4 + 3][d] = v.w;
            }
        }
        {
            int rg = tid & 1;
            int j  = (tid >> 1) & 3;
            int ebase = tid >> 3;
#pragma unroll
            for (int r = 0; r < 4; r++) {
                int e = ebase + 32 * r;
                const float* px = x + ((size_t)bb * CHN + 128 * j + e) * NPOS + posb + rg * 4;
                float4 v = *(const float4*)px;
                Bs[(rg * 4 + 0) * 4 + j][e] = v.x;
                Bs[(rg * 4 + 1) * 4 + j][e] = v.y;
                Bs[(rg * 4 + 2) * 4 + j][e] = v.z;
                Bs[(rg * 4 + 3) * 4 + j][e] = v.w;
            }
        }
        __syncthreads();

#pragma unroll
        for (int m = 0; m < 32; m++) {
            float a[8];
            *(float4*)&a[0]  = *(const float4*)&As[m][ty * 4];
            *(float4*)&a[4]  = *(const float4*)&As[m][64 + ty * 4];
            float4 b0 = *(const float4*)&Bs[m][tx * 4];
            float4 b1 = *(const float4*)&Bs[m][64 + tx * 4];
            unsigned long long bb4[4];
            bb4[0] = pack2(b0.x, b0.y);
            bb4[1] = pack2(b0.z, b0.w);
            bb4[2] = pack2(b1.x, b1.y);
            bb4[3] = pack2(b1.z, b1.w);
#pragma unroll
            for (int i = 0; i < 8; i++) {
                unsigned long long aa = pack2(a[i], a[i]);
                ffma2(acc2[i][0], aa, bb4[0]);
                ffma2(acc2[i][1], aa, bb4[1]);
                ffma2(acc2[i][2], aa, bb4[2]);
                ffma2(acc2[i][3], aa, bb4[3]);
            }
        }
        __syncthreads();
    }

    float* dst = &g_kvp[(((size_t)(bb * HEADS + hh)) * KV_SPLIT + chunk) * HD * HD];
#pragma unroll
    for (int ih = 0; ih < 2; ih++) {
#pragma unroll
        for (int i2 = 0; i2 < 4; i2++) {
            int i = ih * 4 + i2;
            int d = ih * 64 + ty * 4 + i2;
#pragma unroll
            for (int jh = 0; jh < 2; jh++) {
                float lo0, hi0, lo1, hi1;
                unpack2(acc2[i][jh * 2 + 0], lo0, hi0);
                unpack2(acc2[i][jh * 2 + 1], lo1, hi1);
                float4 o;
                o.x = lo0;
                o.y = hi0;
                o.z = lo1;
                o.w = hi1;
                *(float4*)&dst[d * HD + jh * 64 + tx * 4] = o;
            }
        }
    }
}

__global__ void kvreduce_kernel() {
    int idx = blockIdx.x * 256 + threadIdx.x;
    int bh  = idx >> 14;
    int off = idx & 16383;
    const float* p = &g_kvp[((size_t)bh * KV_SPLIT) * HD * HD + off];
    float s = 0.f;
#pragma unroll
    for (int c = 0; c < KV_SPLIT; c++) s += p[(size_t)c * HD * HD];
    g_kv[idx] = s * (1.f / NPOS);
}

// ============================================================================
// Kernel 6: out = z * (q_rope @ kv)   (fma.rn.f32x2 microkernel)
// ============================================================================
__global__ __launch_bounds__(256) void out_kernel(float* __restrict__ out) {
    const int m0 = blockIdx.x * 128;
    const int hh = blockIdx.y, bb = blockIdx.z;
    __shared__ float Qs[16][132];
    __shared__ float Es[16][132];
    const int tid = threadIdx.x;
    const int tx = tid & 15, ty = tid >> 4;

    unsigned long long acc2[8][4];    // [i = e-index][pair of m]
#pragma unroll
    for (int i = 0; i < 8; i++)
#pragma unroll
        for (int j = 0; j < 4; j++) acc2[i][j] = 0ull;

    const float* qr = &g_q[((size_t)bb * CHN + 128 * hh) * NPOS];
    const float* kv = &g_kv[((size_t)(bb * HEADS) + hh) * HD * HD];

    for (int d0 = 0; d0 < HD; d0 += 16) {
#pragma unroll
        for (int r = 0; r < 2; r++) {
            int idx = tid + r * 256;
            int dk = idx >> 5;
            int mg = (idx & 31) * 4;
            *(float4*)&Qs[dk][mg] = *(const float4*)&qr[(size_t)(d0 + dk) * NPOS + m0 + mg];
            *(float4*)&Es[dk][mg] = *(const float4*)&kv[(d0 + dk) * HD + mg];
        }
        __syncthreads();
#pragma unroll
        for (int dk = 0; dk < 16; dk++) {
            float ev[8];
            *(float4*)&ev[0] = *(const float4*)&Es[dk][ty * 4];
            *(float4*)&ev[4] = *(const float4*)&Es[dk][64 + ty * 4];
            float4 m0v = *(const float4*)&Qs[dk][tx * 4];
            float4 m1v = *(const float4*)&Qs[dk][64 + tx * 4];
            unsigned long long mm[4];
            mm[0] = pack2(m0v.x, m0v.y);
            mm[1] = pack2(m0v.z, m0v.w);
            mm[2] = pack2(m1v.x, m1v.y);
            mm[3] = pack2(m1v.z, m1v.w);
#pragma unroll
            for (int i = 0; i < 8; i++) {
                unsigned long long ee = pack2(ev[i], ev[i]);
                ffma2(acc2[i][0], ee, mm[0]);
                ffma2(acc2[i][1], ee, mm[1]);
                ffma2(acc2[i][2], ee, mm[2]);
                ffma2(acc2[i][3], ee, mm[3]);
            }
        }
        __syncthreads();
    }

    const float* zb = &g_z[((size_t)bb * HEADS + hh) * NPOS + m0];
#pragma unroll
    for (int ih = 0; ih < 2; ih++) {
#pragma unroll
        for (int i2 = 0; i2 < 4; i2++) {
            int i = ih * 4 + i2;
            int e = ih * 64 + ty * 4 + i2;
            float* dst = out + ((size_t)bb * CHN + 128 * hh + e) * NPOS + m0;
#pragma unroll
            for (int jh = 0; jh < 2; jh++) {
                int mc = jh * 64 + tx * 4;
                float lo0, hi0, lo1, hi1;
                unpack2(acc2[i][jh * 2 + 0], lo0, hi0);
                unpack2(acc2[i][jh * 2 + 1], lo1, hi1);
                float4 o;
                o.x = lo0 * zb[mc + 0];
                o.y = hi0 * zb[mc + 1];
                o.z = lo1 * zb[mc + 2];
                o.w = hi1 * zb[mc + 3];
                *(float4*)&dst[mc] = o;
            }
        }
    }
}

// ============================================================================
// Kernel 7: lepe — depthwise 3x3 conv, out += conv + bias
// ============================================================================
__global__ __launch_bounds__(256) void lepe_kernel(const float* __restrict__ x,
                                                   const float* __restrict__ w,
                                                   const float* __restrict__ bias,
                                                   float* __restrict__ out) {
    const int c = blockIdx.x, bb = blockIdx.y;
    __shared__ float plane[NPOS];
    const float* src = x + ((size_t)bb * CHN + c) * NPOS;
    const int tid = threadIdx.x;
    for (int i = tid; i < NPOS; i += 256) plane[i] = src[i];
    float wv[9];
#pragma unroll
    for (int kk = 0; kk < 9; kk++) wv[kk] = w[c * 9 + kk];
    const float bv = bias[c];
    __syncthreads();

    float* dst = out + ((size_t)bb * CHN + c) * NPOS;
    for (int i = tid; i < NPOS; i += 256) {
        int y = i / IMGW;
        int xx = i - y * IMGW;
        float s = bv;
#pragma unroll
        for (int ky = 0; ky < 3; ky++) {
            int yy = y + ky - 1;
            if (yy < 0 || yy >= IMGW) continue;
#pragma unroll
            for (int kx = 0; kx < 3; kx++) {
                int xs = xx + kx - 1;
                if (xs < 0 || xs >= IMGW) continue;
                s += wv[ky * 3 + kx] * plane[yy * IMGW + xs];
            }
        }
        dst[i] += s;
    }
}

// ============================================================================
extern "C" void kernel_launch(void* const* d_in, const int* in_sizes, int n_in,
                              void* d_out, int out_size) {
    (void)in_sizes; (void)n_in; (void)out_size;
    const float* x    = (const float*)d_in[0];
    const float* Wqk  = (const float*)d_in[1];
    const float* bqk  = (const float*)d_in[2];
    const float* lw   = (const float*)d_in[3];
    const float* lb   = (const float*)d_in[4];
    float* out = (float*)d_out;

    // 1) q,k = elu(W_qk @ x + b) + 1, channels-first
    qk_gemm_kernel<<<dim3(72, 8, BATCH), 256>>>(x, Wqk, bqk);
    // 2) k_mean (raw k)
    colsum_kernel<<<dim3(CHN, BATCH), 256>>>();
    kmean_kernel<<<16, 256>>>();
    // 3) z (raw q)
    z_kernel<<<dim3(9, HEADS, BATCH), 256>>>();
    // 4) RoPE in place
    rope_kernel<<<dim3(NPOS / 256, CHN / 2, BATCH * 2), 256>>>();
    // 5) kv (split-K + deterministic reduce)
    kv_kernel<<<dim3(KV_SPLIT, HEADS, BATCH), 256>>>(x);
    kvreduce_kernel<<<2048, 256>>>();
    // 6) out = z * (q_rope @ kv)
    out_kernel<<<dim3(72, HEADS, BATCH), 256>>>(out);
    // 7) out += depthwise3x3(x) + bias
    lepe_kernel<<<dim3(CHN, BATCH), 256>>>(x, lw, lb, out);
}